// round 3
// baseline (speedup 1.0000x reference)
#include <cuda_runtime.h>
#include <math.h>

// Problem constants
#define BD   2
#define SEQ  2048
#define DIM  1024
#define NH   16
#define HD   64
#define MROWS (BD * SEQ)          // 4096
#define SCALE 0.125f              // HD^-0.5

// Scratch (allocation-free rule: __device__ globals)
static __device__ float g_Q[MROWS * DIM];
static __device__ float g_K[MROWS * DIM];
static __device__ float g_V[MROWS * DIM];
static __device__ float g_A[MROWS * DIM];

// ---------------------------------------------------------------------------
// GEMM (NT): C[m,e] = sum_k A[m,k] * W[e,k] (+ bias[e])
// A: [M, K] row-major, W: [E, K] row-major.  M=4096, E=K=1024.
// 128x128 block tile, BK=16, 256 threads, 8x8 per-thread register tile.
// Double-buffered smem: global loads for tile t+1 overlap FMAs of tile t.
// blockIdx.z selects among up to 3 (W, C) pairs (fused Q/K/V projections).
// ---------------------------------------------------------------------------
__global__ __launch_bounds__(256)
void gemm_nt(const float* __restrict__ A,
             const float* __restrict__ W0, const float* __restrict__ W1,
             const float* __restrict__ W2,
             float* __restrict__ C0, float* __restrict__ C1, float* __restrict__ C2,
             const float* __restrict__ bias)
{
    const float* W = (blockIdx.z == 0) ? W0 : (blockIdx.z == 1) ? W1 : W2;
    float*       C = (blockIdx.z == 0) ? C0 : (blockIdx.z == 1) ? C1 : C2;

    __shared__ float As[2][16][132];   // [buf][k][m], padded stride 132
    __shared__ float Ws[2][16][132];   // [buf][k][e]

    const int tid  = threadIdx.x;
    const int ty   = tid >> 4;      // 0..15
    const int tx   = tid & 15;      // 0..15
    const int brow = blockIdx.y * 128;
    const int bcol = blockIdx.x * 128;

    // this thread's two load slots (row, col4) within a 128x16 tile
    const int r0 = tid >> 2;             // 0..63
    const int r1 = r0 + 64;              // 64..127
    const int c4 = (tid & 3) * 4;        // 0,4,8,12

    const float* Arow0 = &A[(size_t)(brow + r0) * DIM + c4];
    const float* Arow1 = &A[(size_t)(brow + r1) * DIM + c4];
    const float* Wrow0 = &W[(size_t)(bcol + r0) * DIM + c4];
    const float* Wrow1 = &W[(size_t)(bcol + r1) * DIM + c4];

    float acc[8][8];
#pragma unroll
    for (int i = 0; i < 8; i++)
#pragma unroll
        for (int j = 0; j < 8; j++) acc[i][j] = 0.0f;

    // prologue: load tile 0 into buf 0
    {
        float4 a0 = *(const float4*)(Arow0);
        float4 a1 = *(const float4*)(Arow1);
        float4 w0 = *(const float4*)(Wrow0);
        float4 w1 = *(const float4*)(Wrow1);
        As[0][c4 + 0][r0] = a0.x; As[0][c4 + 1][r0] = a0.y;
        As[0][c4 + 2][r0] = a0.z; As[0][c4 + 3][r0] = a0.w;
        As[0][c4 + 0][r1] = a1.x; As[0][c4 + 1][r1] = a1.y;
        As[0][c4 + 2][r1] = a1.z; As[0][c4 + 3][r1] = a1.w;
        Ws[0][c4 + 0][r0] = w0.x; Ws[0][c4 + 1][r0] = w0.y;
        Ws[0][c4 + 2][r0] = w0.z; Ws[0][c4 + 3][r0] = w0.w;
        Ws[0][c4 + 0][r1] = w1.x; Ws[0][c4 + 1][r1] = w1.y;
        Ws[0][c4 + 2][r1] = w1.z; Ws[0][c4 + 3][r1] = w1.w;
    }
    __syncthreads();

    int buf = 0;
    for (int k0 = 0; k0 < DIM; k0 += 16) {
        const bool has_next = (k0 + 16) < DIM;
        float4 a0, a1, w0, w1;
        if (has_next) {
            int off = k0 + 16;
            a0 = *(const float4*)(Arow0 + off);
            a1 = *(const float4*)(Arow1 + off);
            w0 = *(const float4*)(Wrow0 + off);
            w1 = *(const float4*)(Wrow1 + off);
        }

#pragma unroll
        for (int k = 0; k < 16; k++) {
            float a[8], b[8];
            *(float4*)&a[0] = *(const float4*)&As[buf][k][ty * 8];
            *(float4*)&a[4] = *(const float4*)&As[buf][k][ty * 8 + 4];
            *(float4*)&b[0] = *(const float4*)&Ws[buf][k][tx * 8];
            *(float4*)&b[4] = *(const float4*)&Ws[buf][k][tx * 8 + 4];
#pragma unroll
            for (int i = 0; i < 8; i++)
#pragma unroll
                for (int j = 0; j < 8; j++)
                    acc[i][j] = fmaf(a[i], b[j], acc[i][j]);
        }

        if (has_next) {
            int nb = buf ^ 1;
            As[nb][c4 + 0][r0] = a0.x; As[nb][c4 + 1][r0] = a0.y;
            As[nb][c4 + 2][r0] = a0.z; As[nb][c4 + 3][r0] = a0.w;
            As[nb][c4 + 0][r1] = a1.x; As[nb][c4 + 1][r1] = a1.y;
            As[nb][c4 + 2][r1] = a1.z; As[nb][c4 + 3][r1] = a1.w;
            Ws[nb][c4 + 0][r0] = w0.x; Ws[nb][c4 + 1][r0] = w0.y;
            Ws[nb][c4 + 2][r0] = w0.z; Ws[nb][c4 + 3][r0] = w0.w;
            Ws[nb][c4 + 0][r1] = w1.x; Ws[nb][c4 + 1][r1] = w1.y;
            Ws[nb][c4 + 2][r1] = w1.z; Ws[nb][c4 + 3][r1] = w1.w;
            __syncthreads();
            buf = nb;
        }
    }

#pragma unroll
    for (int i = 0; i < 8; i++) {
        size_t r = (size_t)(brow + ty * 8 + i);
#pragma unroll
        for (int j = 0; j < 8; j += 4) {
            int c = bcol + tx * 8 + j;
            float4 v = make_float4(acc[i][j], acc[i][j + 1], acc[i][j + 2], acc[i][j + 3]);
            if (bias) {
                v.x += bias[c]; v.y += bias[c + 1]; v.z += bias[c + 2]; v.w += bias[c + 3];
            }
            *(float4*)&C[r * DIM + c] = v;
        }
    }
}

// ---------------------------------------------------------------------------
// Flash attention, one (b,h) per blockIdx.y, one 64-query tile per blockIdx.x.
// 256 threads as 16x16; each thread owns a 4(row)x4(col) fragment.
// K/V tiles are register-prefetched one iteration ahead so their global-load
// latency overlaps the current tile's S/softmax/PV compute.
// smem (dynamic): Qt[d][i], Kt[d][j], Vs[j][d], Pt[j][i], all [64][68].
// ---------------------------------------------------------------------------
#define FSTRIDE 68
#define FTILE_F (64 * FSTRIDE)
#define FLASH_SMEM (4 * FTILE_F * 4)   // bytes = 69632

__device__ __forceinline__ float warp16_max(float v) {
#pragma unroll
    for (int m = 8; m >= 1; m >>= 1)
        v = fmaxf(v, __shfl_xor_sync(0xffffffffu, v, m));
    return v;
}
__device__ __forceinline__ float warp16_sum(float v) {
#pragma unroll
    for (int m = 8; m >= 1; m >>= 1)
        v += __shfl_xor_sync(0xffffffffu, v, m);
    return v;
}

__global__ __launch_bounds__(256)
void flash_attn(const float* __restrict__ Q, const float* __restrict__ K,
                const float* __restrict__ V, float* __restrict__ Out)
{
    extern __shared__ float sm[];
    float (*Qt)[FSTRIDE] = (float(*)[FSTRIDE])(sm);
    float (*Kt)[FSTRIDE] = (float(*)[FSTRIDE])(sm + 1 * FTILE_F);
    float (*Vs)[FSTRIDE] = (float(*)[FSTRIDE])(sm + 2 * FTILE_F);
    float (*Pt)[FSTRIDE] = (float(*)[FSTRIDE])(sm + 3 * FTILE_F);

    const int tid = threadIdx.x;
    const int ty  = tid >> 4;     // query-row group 0..15
    const int tx  = tid & 15;     // col group 0..15

    const int qbase = blockIdx.x * 64;
    const int bh    = blockIdx.y;            // 0..31
    const int b     = bh / NH;
    const int h     = bh % NH;
    const size_t rowbase = (size_t)b * SEQ;  // row into [4096, DIM]
    const int cbase = h * HD;

    // Load Q tile transposed: Qt[d][i]
    for (int idx = tid; idx < 64 * HD; idx += 256) {
        int i = idx >> 6, d = idx & 63;
        Qt[d][i] = Q[(rowbase + qbase + i) * DIM + cbase + d];
    }

    // Per-thread K/V prefetch slots: 4 float4 each.
    // slot = tid + t*256 (0..1023): j = slot>>4 (0..63), d4 = (slot&15)*4.
    const int pj[4]  = { tid >> 4, (tid + 256) >> 4, (tid + 512) >> 4, (tid + 768) >> 4 };
    const int pd4    = (tid & 15) * 4;

    float4 kp[4], vp[4];
    // prefetch tile 0
#pragma unroll
    for (int t = 0; t < 4; t++) {
        size_t grow = (rowbase + 0 + pj[t]) * DIM + cbase + pd4;
        kp[t] = *(const float4*)&K[grow];
        vp[t] = *(const float4*)&V[grow];
    }

    float m_run[4], l_run[4], acc[4][4];
#pragma unroll
    for (int r = 0; r < 4; r++) {
        m_run[r] = -1e30f; l_run[r] = 0.0f;
#pragma unroll
        for (int c = 0; c < 4; c++) acc[r][c] = 0.0f;
    }

    for (int kt = 0; kt < SEQ; kt += 64) {
        __syncthreads();   // previous iteration's reads of Kt/Vs/Pt are done
        // commit prefetched K/V tile to smem
#pragma unroll
        for (int t = 0; t < 4; t++) {
            Kt[pd4 + 0][pj[t]] = kp[t].x; Kt[pd4 + 1][pj[t]] = kp[t].y;
            Kt[pd4 + 2][pj[t]] = kp[t].z; Kt[pd4 + 3][pj[t]] = kp[t].w;
            *(float4*)&Vs[pj[t]][pd4] = vp[t];
        }
        __syncthreads();

        // issue next tile's loads now; scoreboard resolves during compute below
        if (kt + 64 < SEQ) {
#pragma unroll
            for (int t = 0; t < 4; t++) {
                size_t grow = (rowbase + kt + 64 + pj[t]) * DIM + cbase + pd4;
                kp[t] = *(const float4*)&K[grow];
                vp[t] = *(const float4*)&V[grow];
            }
        }

        // S = Q K^T (64x64), per-thread 4x4 fragment
        float s[4][4];
#pragma unroll
        for (int r = 0; r < 4; r++)
#pragma unroll
            for (int c = 0; c < 4; c++) s[r][c] = 0.0f;

#pragma unroll 4
        for (int d = 0; d < HD; d++) {
            float qa[4], ka[4];
            *(float4*)qa = *(const float4*)&Qt[d][ty * 4];
            *(float4*)ka = *(const float4*)&Kt[d][tx * 4];
#pragma unroll
            for (int r = 0; r < 4; r++)
#pragma unroll
                for (int c = 0; c < 4; c++)
                    s[r][c] = fmaf(qa[r], ka[c], s[r][c]);
        }

        // online softmax (rows split across the 16 tx lanes of each half-warp)
#pragma unroll
        for (int r = 0; r < 4; r++) {
            float rm = -1e30f;
#pragma unroll
            for (int c = 0; c < 4; c++) {
                s[r][c] *= SCALE;
                rm = fmaxf(rm, s[r][c]);
            }
            rm = warp16_max(rm);
            float mn   = fmaxf(m_run[r], rm);
            float corr = __expf(m_run[r] - mn);
            m_run[r] = mn;
            float rs = 0.0f;
#pragma unroll
            for (int c = 0; c < 4; c++) {
                s[r][c] = __expf(s[r][c] - mn);
                rs += s[r][c];
            }
            rs = warp16_sum(rs);
            l_run[r] = l_run[r] * corr + rs;
#pragma unroll
            for (int c = 0; c < 4; c++) acc[r][c] *= corr;
        }

        // stash P transposed: Pt[j][i]
#pragma unroll
        for (int r = 0; r < 4; r++)
#pragma unroll
            for (int c = 0; c < 4; c++)
                Pt[tx * 4 + c][ty * 4 + r] = s[r][c];
        __syncthreads();

        // O += P V : acc rows ty*4.., d-cols tx*4..
#pragma unroll 4
        for (int j = 0; j < 64; j++) {
            float pa[4], va[4];
            *(float4*)pa = *(const float4*)&Pt[j][ty * 4];
            *(float4*)va = *(const float4*)&Vs[j][tx * 4];
#pragma unroll
            for (int r = 0; r < 4; r++)
#pragma unroll
                for (int c = 0; c < 4; c++)
                    acc[r][c] = fmaf(pa[r], va[c], acc[r][c]);
        }
    }

    // epilogue: normalize and store to (b, n, h*HD + d) layout
#pragma unroll
    for (int r = 0; r < 4; r++) {
        float inv = 1.0f / l_run[r];
        size_t row = rowbase + qbase + ty * 4 + r;
        float4 o = make_float4(acc[r][0] * inv, acc[r][1] * inv,
                               acc[r][2] * inv, acc[r][3] * inv);
        *(float4*)&Out[row * DIM + cbase + tx * 4] = o;
    }
}

// ---------------------------------------------------------------------------
// launch
// ---------------------------------------------------------------------------
extern "C" void kernel_launch(void* const* d_in, const int* in_sizes, int n_in,
                              void* d_out, int out_size)
{
    const float* x  = (const float*)d_in[0];
    const float* Wq = (const float*)d_in[1];
    const float* Wk = (const float*)d_in[2];
    const float* Wv = (const float*)d_in[3];
    const float* Wo = (const float*)d_in[4];
    const float* bo = (const float*)d_in[5];
    float* out = (float*)d_out;

    float *Qp, *Kp, *Vp, *Ap;
    cudaGetSymbolAddress((void**)&Qp, g_Q);
    cudaGetSymbolAddress((void**)&Kp, g_K);
    cudaGetSymbolAddress((void**)&Vp, g_V);
    cudaGetSymbolAddress((void**)&Ap, g_A);

    cudaFuncSetAttribute(flash_attn, cudaFuncAttributeMaxDynamicSharedMemorySize,
                         FLASH_SMEM);

    // 1) fused Q/K/V projections
    dim3 gQKV(DIM / 128, MROWS / 128, 3);
    gemm_nt<<<gQKV, 256>>>(x, Wq, Wk, Wv, Qp, Kp, Vp, nullptr);

    // 2) attention
    dim3 gF(SEQ / 64, BD * NH);
    flash_attn<<<gF, 256, FLASH_SMEM>>>(Qp, Kp, Vp, Ap);

    // 3) output projection + bias
    dim3 gO(DIM / 128, MROWS / 128, 1);
    gemm_nt<<<gO, 256>>>(Ap, Wo, Wo, Wo, out, out, out, bo);
}

// round 6
// speedup vs baseline: 1.2402x; 1.2402x over previous
#include <cuda_runtime.h>
#include <math.h>
#include <stdint.h>

// Problem constants
#define BD   2
#define SEQ  2048
#define DIM  1024
#define NH   16
#define HD   64
#define MROWS (BD * SEQ)          // 4096
#define SCALE 0.125f              // HD^-0.5

// Scratch (allocation-free rule: __device__ globals)
static __device__ float g_Q[MROWS * DIM];
static __device__ float g_K[MROWS * DIM];
static __device__ float g_V[MROWS * DIM];
static __device__ float g_A[MROWS * DIM];

// ---------------------------------------------------------------------------
// tf32 helpers
// ---------------------------------------------------------------------------
__device__ __forceinline__ uint32_t f2tf(float x) {
    uint32_t u;
    asm("cvt.rna.tf32.f32 %0, %1;" : "=r"(u) : "f"(x));
    return u;
}

#define MMA_TF32(d, a, b)                                                     \
    asm volatile(                                                             \
        "mma.sync.aligned.m16n8k8.row.col.f32.tf32.tf32.f32 "                 \
        "{%0,%1,%2,%3}, {%4,%5,%6,%7}, {%8,%9}, {%0,%1,%2,%3};"               \
        : "+f"(d[0]), "+f"(d[1]), "+f"(d[2]), "+f"(d[3])                      \
        : "r"(a[0]), "r"(a[1]), "r"(a[2]), "r"(a[3]), "r"(b[0]), "r"(b[1]))

// ---------------------------------------------------------------------------
// Tensor-core GEMM (NT): C[m,e] = sum_k A[m,k] * W[e,k] (+ bias[e])
// tf32 mma.sync m16n8k8, 3-term split (Ah*Wh + Ah*Wl + Al*Wh).
// 128x128 block tile, BK=16, 8 warps, 64x32 warp tile, double-buffered smem.
// ---------------------------------------------------------------------------
#define SKS   20                         // smem k-stride (uint32 units)
#define SBUF  (128 * SKS)
#define SARR  (2 * SBUF)
#define GEMM_SMEM (4 * SARR * 4)         // 81920 B
#define SIDX(buf, m, k) ((buf) * SBUF + (m) * SKS + (k))

__global__ __launch_bounds__(256)
void gemm_tf32(const float* __restrict__ A,
               const float* __restrict__ W0, const float* __restrict__ W1,
               const float* __restrict__ W2,
               float* __restrict__ C0, float* __restrict__ C1, float* __restrict__ C2,
               const float* __restrict__ bias)
{
    const float* W = (blockIdx.z == 0) ? W0 : (blockIdx.z == 1) ? W1 : W2;
    float*       C = (blockIdx.z == 0) ? C0 : (blockIdx.z == 1) ? C1 : C2;

    extern __shared__ uint32_t smx[];
    uint32_t* sAh = smx;
    uint32_t* sAl = smx + 1 * SARR;
    uint32_t* sWh = smx + 2 * SARR;
    uint32_t* sWl = smx + 3 * SARR;

    const int tid  = threadIdx.x;
    const int brow = blockIdx.y * 128;
    const int bcol = blockIdx.x * 128;

    const int lane = tid & 31;
    const int g    = lane >> 2;
    const int tg   = lane & 3;
    const int wm   = ((tid >> 5) & 1) * 64;
    const int wn   = (tid >> 6) * 32;

    const int sm0 = tid >> 2;
    const int sm1 = sm0 + 64;
    const int sc4 = (tid & 3) * 4;

    const float* Arow0 = &A[(size_t)(brow + sm0) * DIM + sc4];
    const float* Arow1 = &A[(size_t)(brow + sm1) * DIM + sc4];
    const float* Wrow0 = &W[(size_t)(bcol + sm0) * DIM + sc4];
    const float* Wrow1 = &W[(size_t)(bcol + sm1) * DIM + sc4];

    float acc[4][4][4];
#pragma unroll
    for (int mi = 0; mi < 4; mi++)
#pragma unroll
        for (int ni = 0; ni < 4; ni++)
#pragma unroll
            for (int r = 0; r < 4; r++) acc[mi][ni][r] = 0.0f;

    auto stage = [&](uint32_t* hi, uint32_t* lo, int buf, int m, float4 v) {
        uint4 h, l;
        h.x = f2tf(v.x); l.x = f2tf(v.x - __uint_as_float(h.x));
        h.y = f2tf(v.y); l.y = f2tf(v.y - __uint_as_float(h.y));
        h.z = f2tf(v.z); l.z = f2tf(v.z - __uint_as_float(h.z));
        h.w = f2tf(v.w); l.w = f2tf(v.w - __uint_as_float(h.w));
        *(uint4*)&hi[SIDX(buf, m, sc4)] = h;
        *(uint4*)&lo[SIDX(buf, m, sc4)] = l;
    };

    stage(sAh, sAl, 0, sm0, *(const float4*)(Arow0));
    stage(sAh, sAl, 0, sm1, *(const float4*)(Arow1));
    stage(sWh, sWl, 0, sm0, *(const float4*)(Wrow0));
    stage(sWh, sWl, 0, sm1, *(const float4*)(Wrow1));
    __syncthreads();

    int buf = 0;
    for (int k0 = 0; k0 < DIM; k0 += 16) {
        const bool has_next = (k0 + 16) < DIM;
        float4 pa0, pa1, pw0, pw1;
        if (has_next) {
            int off = k0 + 16;
            pa0 = *(const float4*)(Arow0 + off);
            pa1 = *(const float4*)(Arow1 + off);
            pw0 = *(const float4*)(Wrow0 + off);
            pw1 = *(const float4*)(Wrow1 + off);
        }

#pragma unroll
        for (int ks = 0; ks < 16; ks += 8) {
            uint32_t ah[4][4], al[4][4], bh[4][2], bl[4][2];
#pragma unroll
            for (int mi = 0; mi < 4; mi++) {
                int r = wm + mi * 16 + g;
                int c = ks + tg;
                ah[mi][0] = sAh[SIDX(buf, r,     c)];
                ah[mi][1] = sAh[SIDX(buf, r + 8, c)];
                ah[mi][2] = sAh[SIDX(buf, r,     c + 4)];
                ah[mi][3] = sAh[SIDX(buf, r + 8, c + 4)];
                al[mi][0] = sAl[SIDX(buf, r,     c)];
                al[mi][1] = sAl[SIDX(buf, r + 8, c)];
                al[mi][2] = sAl[SIDX(buf, r,     c + 4)];
                al[mi][3] = sAl[SIDX(buf, r + 8, c + 4)];
            }
#pragma unroll
            for (int ni = 0; ni < 4; ni++) {
                int r = wn + ni * 8 + g;
                int c = ks + tg;
                bh[ni][0] = sWh[SIDX(buf, r, c)];
                bh[ni][1] = sWh[SIDX(buf, r, c + 4)];
                bl[ni][0] = sWl[SIDX(buf, r, c)];
                bl[ni][1] = sWl[SIDX(buf, r, c + 4)];
            }
#pragma unroll
            for (int mi = 0; mi < 4; mi++)
#pragma unroll
                for (int ni = 0; ni < 4; ni++) {
                    MMA_TF32(acc[mi][ni], ah[mi], bh[ni]);
                    MMA_TF32(acc[mi][ni], ah[mi], bl[ni]);
                    MMA_TF32(acc[mi][ni], al[mi], bh[ni]);
                }
        }

        if (has_next) {
            int nb = buf ^ 1;
            stage(sAh, sAl, nb, sm0, pa0);
            stage(sAh, sAl, nb, sm1, pa1);
            stage(sWh, sWl, nb, sm0, pw0);
            stage(sWh, sWl, nb, sm1, pw1);
            __syncthreads();
            buf = nb;
        }
    }

#pragma unroll
    for (int mi = 0; mi < 4; mi++) {
#pragma unroll
        for (int ni = 0; ni < 4; ni++) {
            int row = brow + wm + mi * 16 + g;
            int col = bcol + wn + ni * 8 + 2 * tg;
            float bx = 0.0f, by = 0.0f;
            if (bias) { bx = bias[col]; by = bias[col + 1]; }
            float2 v01 = make_float2(acc[mi][ni][0] + bx, acc[mi][ni][1] + by);
            float2 v23 = make_float2(acc[mi][ni][2] + bx, acc[mi][ni][3] + by);
            *(float2*)&C[(size_t)row * DIM + col]       = v01;
            *(float2*)&C[(size_t)(row + 8) * DIM + col] = v23;
        }
    }
}

// ---------------------------------------------------------------------------
// Tensor-core flash attention (tf32 mma, 3-term split everywhere).
// CTA: 128 queries x full head; key tiles of 64. 8 warps, warp w owns q-rows
// [16w, 16w+16) as mma m-dim; n-dim = 64 keys (QK) or 64 head-dims (PV).
// smem (stride 68, conflict-free frag loads: bank = (4*row+col)%32):
//   sQh/sQl [128][68]   Q[i][d] (A-frag source, QK)
//   sKh/sKl [64][68]    K[j][d] (B-frag source [n=j][k=d], QK)
//   sVh/sVl [64][68]    V^T[d][j] (B-frag source [n=d][k=j], PV)
//   sPh/sPl [128][68]   P[i][j] (A-frag source, PV; per-warp private rows)
// K/V register-prefetched one tile ahead (field-tested R2 pattern).
// ---------------------------------------------------------------------------
#define FQ   128
#define FST  68
#define QH_OFF 0
#define QL_OFF (128 * FST)               // 8704
#define KH_OFF (2 * 128 * FST)           // 17408
#define KL_OFF (KH_OFF + 64 * FST)
#define VH_OFF (KH_OFF + 2 * 64 * FST)
#define VL_OFF (KH_OFF + 3 * 64 * FST)
#define PH_OFF (KH_OFF + 4 * 64 * FST)   // 34816
#define PL_OFF (PH_OFF + 128 * FST)
#define FLASH_SMEM ((PH_OFF + 2 * 128 * FST) * 4)   // 208896 B

__global__ __launch_bounds__(256)
void flash_tf32(const float* __restrict__ Q, const float* __restrict__ K,
                const float* __restrict__ V, float* __restrict__ Out)
{
    extern __shared__ uint32_t fsm[];
    uint32_t* sQh = fsm + QH_OFF;
    uint32_t* sQl = fsm + QL_OFF;
    uint32_t* sKh = fsm + KH_OFF;
    uint32_t* sKl = fsm + KL_OFF;
    uint32_t* sVh = fsm + VH_OFF;
    uint32_t* sVl = fsm + VL_OFF;
    uint32_t* sPh = fsm + PH_OFF;
    uint32_t* sPl = fsm + PL_OFF;

    const int tid  = threadIdx.x;
    const int lane = tid & 31;
    const int g    = lane >> 2;
    const int tg   = lane & 3;
    const int wq   = (tid >> 5) * 16;       // warp's q-row offset in CTA tile

    const int qbase = blockIdx.x * FQ;
    const int bh    = blockIdx.y;
    const int b     = bh / NH;
    const int h     = bh % NH;
    const size_t rowbase = (size_t)b * SEQ;
    const int cbase = h * HD;

    // load Q tile (128x64), split h/l
    for (int idx = tid; idx < FQ * 16; idx += 256) {
        int row = idx >> 4, c4 = (idx & 15) * 4;
        float4 v = *(const float4*)&Q[(rowbase + qbase + row) * DIM + cbase + c4];
        uint4 hh, ll;
        hh.x = f2tf(v.x); ll.x = f2tf(v.x - __uint_as_float(hh.x));
        hh.y = f2tf(v.y); ll.y = f2tf(v.y - __uint_as_float(hh.y));
        hh.z = f2tf(v.z); ll.z = f2tf(v.z - __uint_as_float(hh.z));
        hh.w = f2tf(v.w); ll.w = f2tf(v.w - __uint_as_float(hh.w));
        *(uint4*)&sQh[row * FST + c4] = hh;
        *(uint4*)&sQl[row * FST + c4] = ll;
    }

    // K/V prefetch: 64x64 tile = 1024 float4, 4 slots/thread
    float4 kp[4], vp[4];
#pragma unroll
    for (int t = 0; t < 4; t++) {
        int s  = tid + t * 256;
        int j  = s >> 4, c4 = (s & 15) * 4;
        size_t ga = (rowbase + 0 + j) * DIM + cbase + c4;
        kp[t] = *(const float4*)&K[ga];
        vp[t] = *(const float4*)&V[ga];
    }

    float m_run[2] = { -1e30f, -1e30f };
    float l_run[2] = { 0.0f, 0.0f };
    float o[8][4];
#pragma unroll
    for (int ni = 0; ni < 8; ni++)
#pragma unroll
        for (int c = 0; c < 4; c++) o[ni][c] = 0.0f;

    for (int kt = 0; kt < SEQ; kt += 64) {
        __syncthreads();   // prior tile's smem reads (K/V/P) complete
        // commit prefetched K (natural) and V (transposed), split h/l
#pragma unroll
        for (int t = 0; t < 4; t++) {
            int s  = tid + t * 256;
            int j  = s >> 4, c4 = (s & 15) * 4;
            uint4 hh, ll;
            hh.x = f2tf(kp[t].x); ll.x = f2tf(kp[t].x - __uint_as_float(hh.x));
            hh.y = f2tf(kp[t].y); ll.y = f2tf(kp[t].y - __uint_as_float(hh.y));
            hh.z = f2tf(kp[t].z); ll.z = f2tf(kp[t].z - __uint_as_float(hh.z));
            hh.w = f2tf(kp[t].w); ll.w = f2tf(kp[t].w - __uint_as_float(hh.w));
            *(uint4*)&sKh[j * FST + c4] = hh;
            *(uint4*)&sKl[j * FST + c4] = ll;
            float vv[4] = { vp[t].x, vp[t].y, vp[t].z, vp[t].w };
#pragma unroll
            for (int q2 = 0; q2 < 4; q2++) {
                uint32_t vh = f2tf(vv[q2]);
                sVh[(c4 + q2) * FST + j] = vh;
                sVl[(c4 + q2) * FST + j] =
                    __float_as_uint(vv[q2] - __uint_as_float(vh));
            }
        }
        __syncthreads();

        // prefetch next tile
        if (kt + 64 < SEQ) {
#pragma unroll
            for (int t = 0; t < 4; t++) {
                int s  = tid + t * 256;
                int j  = s >> 4, c4 = (s & 15) * 4;
                size_t ga = (rowbase + kt + 64 + j) * DIM + cbase + c4;
                kp[t] = *(const float4*)&K[ga];
                vp[t] = *(const float4*)&V[ga];
            }
        }

        // S = Q K^T : warp computes 16x64, 8 n-tiles
        float sf[8][4];
#pragma unroll
        for (int ni = 0; ni < 8; ni++)
#pragma unroll
            for (int c = 0; c < 4; c++) sf[ni][c] = 0.0f;

#pragma unroll
        for (int k0 = 0; k0 < 64; k0 += 8) {
            uint32_t qh[4], ql[4];
            qh[0] = sQh[(wq + g) * FST + k0 + tg];
            qh[1] = sQh[(wq + g + 8) * FST + k0 + tg];
            qh[2] = sQh[(wq + g) * FST + k0 + tg + 4];
            qh[3] = sQh[(wq + g + 8) * FST + k0 + tg + 4];
            ql[0] = sQl[(wq + g) * FST + k0 + tg];
            ql[1] = sQl[(wq + g + 8) * FST + k0 + tg];
            ql[2] = sQl[(wq + g) * FST + k0 + tg + 4];
            ql[3] = sQl[(wq + g + 8) * FST + k0 + tg + 4];
#pragma unroll
            for (int ni = 0; ni < 8; ni++) {
                uint32_t kh[2], kl[2];
                kh[0] = sKh[(ni * 8 + g) * FST + k0 + tg];
                kh[1] = sKh[(ni * 8 + g) * FST + k0 + tg + 4];
                kl[0] = sKl[(ni * 8 + g) * FST + k0 + tg];
                kl[1] = sKl[(ni * 8 + g) * FST + k0 + tg + 4];
                MMA_TF32(sf[ni], qh, kh);
                MMA_TF32(sf[ni], qh, kl);
                MMA_TF32(sf[ni], ql, kh);
            }
        }

        // online softmax, per row-half (c0/c1: row g; c2/c3: row g+8)
#pragma unroll
        for (int hh = 0; hh < 2; hh++) {
            const int c0 = hh * 2, c1 = c0 + 1;
            float rm = -1e30f;
#pragma unroll
            for (int ni = 0; ni < 8; ni++) {
                sf[ni][c0] *= SCALE;
                sf[ni][c1] *= SCALE;
                rm = fmaxf(rm, fmaxf(sf[ni][c0], sf[ni][c1]));
            }
            rm = fmaxf(rm, __shfl_xor_sync(0xffffffffu, rm, 1));
            rm = fmaxf(rm, __shfl_xor_sync(0xffffffffu, rm, 2));
            float mn   = fmaxf(m_run[hh], rm);
            float corr = __expf(m_run[hh] - mn);
            m_run[hh] = mn;
            float rs = 0.0f;
#pragma unroll
            for (int ni = 0; ni < 8; ni++) {
                sf[ni][c0] = __expf(sf[ni][c0] - mn);
                sf[ni][c1] = __expf(sf[ni][c1] - mn);
                rs += sf[ni][c0] + sf[ni][c1];
            }
            rs += __shfl_xor_sync(0xffffffffu, rs, 1);
            rs += __shfl_xor_sync(0xffffffffu, rs, 2);
            l_run[hh] = l_run[hh] * corr + rs;
#pragma unroll
            for (int ni = 0; ni < 8; ni++) {
                o[ni][c0] *= corr;
                o[ni][c1] *= corr;
            }
        }

        // store P split into per-warp smem region (C-frag -> row-major)
#pragma unroll
        for (int ni = 0; ni < 8; ni++) {
#pragma unroll
            for (int c = 0; c < 4; c++) {
                int row = wq + g + ((c >> 1) << 3);
                int col = ni * 8 + 2 * tg + (c & 1);
                uint32_t ph = f2tf(sf[ni][c]);
                sPh[row * FST + col] = ph;
                sPl[row * FST + col] =
                    __float_as_uint(sf[ni][c] - __uint_as_float(ph));
            }
        }
        __syncwarp();

        // O += P V  (A = P row-major [i][j], B = V^T [n=d][k=j])
#pragma unroll
        for (int k0 = 0; k0 < 64; k0 += 8) {
            uint32_t ph[4], pl[4];
            ph[0] = sPh[(wq + g) * FST + k0 + tg];
            ph[1] = sPh[(wq + g + 8) * FST + k0 + tg];
            ph[2] = sPh[(wq + g) * FST + k0 + tg + 4];
            ph[3] = sPh[(wq + g + 8) * FST + k0 + tg + 4];
            pl[0] = sPl[(wq + g) * FST + k0 + tg];
            pl[1] = sPl[(wq + g + 8) * FST + k0 + tg];
            pl[2] = sPl[(wq + g) * FST + k0 + tg + 4];
            pl[3] = sPl[(wq + g + 8) * FST + k0 + tg + 4];
#pragma unroll
            for (int ni = 0; ni < 8; ni++) {
                uint32_t vh[2], vl[2];
                vh[0] = sVh[(ni * 8 + g) * FST + k0 + tg];
                vh[1] = sVh[(ni * 8 + g) * FST + k0 + tg + 4];
                vl[0] = sVl[(ni * 8 + g) * FST + k0 + tg];
                vl[1] = sVl[(ni * 8 + g) * FST + k0 + tg + 4];
                MMA_TF32(o[ni], ph, vh);
                MMA_TF32(o[ni], ph, vl);
                MMA_TF32(o[ni], pl, vh);
            }
        }
    }

    // epilogue: normalize, store (b, n, h*HD + d)
    const float inv0 = 1.0f / l_run[0];
    const float inv1 = 1.0f / l_run[1];
    const size_t row0 = rowbase + qbase + wq + g;
#pragma unroll
    for (int ni = 0; ni < 8; ni++) {
        int col = cbase + ni * 8 + 2 * tg;
        *(float2*)&Out[row0 * DIM + col] =
            make_float2(o[ni][0] * inv0, o[ni][1] * inv0);
        *(float2*)&Out[(row0 + 8) * DIM + col] =
            make_float2(o[ni][2] * inv1, o[ni][3] * inv1);
    }
}

// ---------------------------------------------------------------------------
// launch
// ---------------------------------------------------------------------------
extern "C" void kernel_launch(void* const* d_in, const int* in_sizes, int n_in,
                              void* d_out, int out_size)
{
    const float* x  = (const float*)d_in[0];
    const float* Wq = (const float*)d_in[1];
    const float* Wk = (const float*)d_in[2];
    const float* Wv = (const float*)d_in[3];
    const float* Wo = (const float*)d_in[4];
    const float* bo = (const float*)d_in[5];
    float* out = (float*)d_out;

    float *Qp, *Kp, *Vp, *Ap;
    cudaGetSymbolAddress((void**)&Qp, g_Q);
    cudaGetSymbolAddress((void**)&Kp, g_K);
    cudaGetSymbolAddress((void**)&Vp, g_V);
    cudaGetSymbolAddress((void**)&Ap, g_A);

    cudaFuncSetAttribute(gemm_tf32, cudaFuncAttributeMaxDynamicSharedMemorySize,
                         GEMM_SMEM);
    cudaFuncSetAttribute(flash_tf32, cudaFuncAttributeMaxDynamicSharedMemorySize,
                         FLASH_SMEM);

    // 1) fused Q/K/V projections
    dim3 gQKV(DIM / 128, MROWS / 128, 3);
    gemm_tf32<<<gQKV, 256, GEMM_SMEM>>>(x, Wq, Wk, Wv, Qp, Kp, Vp, nullptr);

    // 2) attention
    dim3 gF(SEQ / FQ, BD * NH);
    flash_tf32<<<gF, 256, FLASH_SMEM>>>(Qp, Kp, Vp, Ap);

    // 3) output projection + bias
    dim3 gO(DIM / 128, MROWS / 128, 1);
    gemm_tf32<<<gO, 256, GEMM_SMEM>>>(Ap, Wo, Wo, Wo, out, out, out, bo);
}